// round 3
// baseline (speedup 1.0000x reference)
#include <cuda_runtime.h>
#include <cuda_bf16.h>

// ---------------------------------------------------------------------------
// GATv2 GNN, 3 layers. CSR-by-dst built per launch; node-parallel softmax+agg.
// edge_index / train_idx are int32 (JAX x64 disabled makes jnp.int64 -> int32).
// ---------------------------------------------------------------------------

#define MAX_N 50000
#define MAX_E 800000

__device__ float g_xl[MAX_N * 256];
__device__ float g_xr[MAX_N * 256];
__device__ float g_h [MAX_N * 256];
__device__ float g_logits[MAX_E * 2];
__device__ int   g_rowptr[MAX_N + 1];
__device__ int   g_cursor[MAX_N];
__device__ int   g_deg   [MAX_N];
__device__ int   g_csrsrc[MAX_E];
__device__ int   g_csrdst[MAX_E];

// ---------------- CSR build ----------------

__global__ void zero_kernel(int* __restrict__ p, int n) {
    int i = blockIdx.x * blockDim.x + threadIdx.x;
    if (i < n) p[i] = 0;
}

__global__ void hist_kernel(const int* __restrict__ dst, int E, int N, int* __restrict__ deg) {
    int e = blockIdx.x * blockDim.x + threadIdx.x;
    if (e >= E) return;
    int d = dst[e];
    if (d >= 0 && d < N) atomicAdd(&deg[d], 1);
}

// Exclusive prefix sum of deg -> rowptr (and cursor copy), single block.
__global__ void scan_kernel(const int* __restrict__ deg, int* __restrict__ rowptr,
                            int* __restrict__ cursor, int n) {
    __shared__ int warp_s[32];
    __shared__ int s_carry;
    int lane = threadIdx.x & 31, wid = threadIdx.x >> 5;
    if (threadIdx.x == 0) s_carry = 0;
    __syncthreads();
    for (int base = 0; base < n; base += 1024) {
        int i = base + threadIdx.x;
        int v = (i < n) ? deg[i] : 0;
        int x = v;
        #pragma unroll
        for (int o = 1; o < 32; o <<= 1) { int t = __shfl_up_sync(0xffffffffu, x, o); if (lane >= o) x += t; }
        if (lane == 31) warp_s[wid] = x;
        __syncthreads();
        if (wid == 0) {
            int y = warp_s[lane];
            #pragma unroll
            for (int o = 1; o < 32; o <<= 1) { int t = __shfl_up_sync(0xffffffffu, y, o); if (lane >= o) y += t; }
            warp_s[lane] = y;
        }
        __syncthreads();
        int off = s_carry + (wid ? warp_s[wid - 1] : 0);
        if (i < n) {
            int excl = off + x - v;
            rowptr[i] = excl;
            cursor[i] = excl;
        }
        int total = warp_s[31];
        __syncthreads();
        if (threadIdx.x == 0) s_carry += total;
        __syncthreads();
    }
    if (threadIdx.x == 0) rowptr[n] = s_carry;
}

__global__ void scatter_kernel(const int* __restrict__ src, const int* __restrict__ dst,
                               int E, int N, int* __restrict__ cursor,
                               int* __restrict__ csrsrc, int* __restrict__ csrdst) {
    int e = blockIdx.x * blockDim.x + threadIdx.x;
    if (e >= E) return;
    int d = dst[e];
    if (d < 0 || d >= N) return;
    int s = src[e];
    int p = atomicAdd(&cursor[d], 1);
    csrsrc[p] = s;
    csrdst[p] = d;
}

// ---------------- GEMM: C[M,N] = A[M,K] @ B[K,N], fp32, row-major ----------------

#define BM 64
#define BN 64
#define BKK 16

__global__ __launch_bounds__(256) void gemm_kernel(
    const float* __restrict__ A, const float* __restrict__ B, float* __restrict__ C,
    int M, int K, int N) {
    __shared__ float As[BKK][BM];
    __shared__ float Bs[BKK][BN];
    int tid = threadIdx.x;
    int tx = tid & 15, ty = tid >> 4;
    int m0 = blockIdx.y * BM, n0 = blockIdx.x * BN;
    float acc[4][4] = {};
    for (int k0 = 0; k0 < K; k0 += BKK) {
        #pragma unroll
        for (int i = tid; i < BM * BKK; i += 256) {
            int mi = i >> 4, ki = i & 15;
            int m = m0 + mi, k = k0 + ki;
            As[ki][mi] = (m < M && k < K) ? A[(long)m * K + k] : 0.f;
        }
        #pragma unroll
        for (int i = tid; i < BKK * BN; i += 256) {
            int ki = i >> 6, ni = i & 63;
            int k = k0 + ki, n = n0 + ni;
            Bs[ki][ni] = (k < K && n < N) ? B[(long)k * N + n] : 0.f;
        }
        __syncthreads();
        #pragma unroll
        for (int kk = 0; kk < BKK; kk++) {
            float a[4], b[4];
            #pragma unroll
            for (int i = 0; i < 4; i++) a[i] = As[kk][ty * 4 + i];
            #pragma unroll
            for (int j = 0; j < 4; j++) b[j] = Bs[kk][tx * 4 + j];
            #pragma unroll
            for (int i = 0; i < 4; i++)
                #pragma unroll
                for (int j = 0; j < 4; j++)
                    acc[i][j] = fmaf(a[i], b[j], acc[i][j]);
        }
        __syncthreads();
    }
    #pragma unroll
    for (int i = 0; i < 4; i++) {
        int m = m0 + ty * 4 + i;
        if (m >= M) continue;
        #pragma unroll
        for (int j = 0; j < 4; j++) {
            int n = n0 + tx * 4 + j;
            if (n < N) C[(long)m * N + n] = acc[i][j];
        }
    }
}

// GEMV: out[m] = dot(A[m,:K], w[:K])
__global__ void gemv_kernel(const float* __restrict__ A, const float* __restrict__ w,
                            float* __restrict__ out, int M, int K) {
    int gt = blockIdx.x * blockDim.x + threadIdx.x;
    int row = gt >> 5, lane = gt & 31;
    if (row >= M) return;
    float s = 0.f;
    for (int k = lane; k < K; k += 32) s = fmaf(A[(long)row * K + k], w[k], s);
    #pragma unroll
    for (int o = 16; o; o >>= 1) s += __shfl_xor_sync(0xffffffffu, s, o);
    if (lane == 0) out[row] = s;
}

// ---------------- Edge logits: warp per edge ----------------

__global__ void edge_logits_kernel(const float* __restrict__ xl, const float* __restrict__ xr,
                                   const float* __restrict__ att,
                                   const int* __restrict__ csrsrc, const int* __restrict__ csrdst,
                                   int E, int H, int C, float* __restrict__ logits) {
    int gt = blockIdx.x * blockDim.x + threadIdx.x;
    int e = gt >> 5, lane = gt & 31;
    if (e >= E) return;
    int s = csrsrc[e], d = csrdst[e];
    int HC = H * C;
    const float* ps = xl + (long)s * HC;
    const float* pd = xr + (long)d * HC;
    for (int h = 0; h < H; h++) {
        float acc = 0.f;
        for (int c = lane; c < C; c += 32) {
            float v = ps[h * C + c] + pd[h * C + c];
            v = v > 0.f ? v : 0.2f * v;
            acc = fmaf(v, att[h * C + c], acc);
        }
        #pragma unroll
        for (int o = 16; o; o >>= 1) acc += __shfl_xor_sync(0xffffffffu, acc, o);
        if (lane == 0) logits[(long)e * H + h] = acc;
    }
}

__global__ void edge3_kernel(const float* __restrict__ xl, const float* __restrict__ xr,
                             const float* __restrict__ att,
                             const int* __restrict__ csrsrc, const int* __restrict__ csrdst,
                             int E, float* __restrict__ logits) {
    int e = blockIdx.x * blockDim.x + threadIdx.x;
    if (e >= E) return;
    float v = xl[csrsrc[e]] + xr[csrdst[e]];
    v = v > 0.f ? v : 0.2f * v;
    logits[e] = v * att[0];
}

// ---------------- Node-parallel softmax + mean aggregate ----------------

__global__ void agg_kernel(const float* __restrict__ xl, const float* __restrict__ logits,
                           const int* __restrict__ rowptr, const int* __restrict__ csrsrc,
                           const float* __restrict__ bias, float* __restrict__ out,
                           int C, int H) {
    int node = blockIdx.x;
    int tid = threadIdx.x;           // H*C threads
    int HC = H * C;
    int h = tid / C;
    int beg = rowptr[node], end = rowptr[node + 1];
    long obase = (long)node * HC + tid;
    if (beg == end) { out[obase] = bias[tid]; return; }
    float m = -1e30f;
    for (int e = beg; e < end; e++) m = fmaxf(m, logits[(long)e * H + h]);
    float s = 0.f, acc = 0.f;
    for (int e = beg; e < end; e++) {
        float w = __expf(logits[(long)e * H + h] - m);
        s += w;
        acc = fmaf(w, xl[(long)csrsrc[e] * HC + tid], acc);
    }
    float deg = (float)(end - beg);
    out[obase] = acc / (s * deg) + bias[tid];
}

__global__ void agg3_kernel(const float* __restrict__ xl, const float* __restrict__ logits,
                            const int* __restrict__ rowptr, const int* __restrict__ csrsrc,
                            const float* __restrict__ bias, float* __restrict__ out, int N) {
    int node = blockIdx.x * blockDim.x + threadIdx.x;
    if (node >= N) return;
    int beg = rowptr[node], end = rowptr[node + 1];
    if (beg == end) { out[node] = bias[0]; return; }
    float m = -1e30f;
    for (int e = beg; e < end; e++) m = fmaxf(m, logits[e]);
    float s = 0.f, acc = 0.f;
    for (int e = beg; e < end; e++) {
        float w = __expf(logits[e] - m);
        s += w;
        acc = fmaf(w, xl[csrsrc[e]], acc);
    }
    out[node] = acc / (s * (float)(end - beg)) + bias[0];
}

// ---------------- Output gather ----------------

__global__ void gather_kernel(const float* __restrict__ h3, const float* __restrict__ y,
                              const int* __restrict__ tidx, int nt, int N,
                              float* __restrict__ out, int both) {
    int i = blockIdx.x * blockDim.x + threadIdx.x;
    if (i >= nt) return;
    int t = tidx[i];
    if (t < 0) t = 0;
    if (t >= N) t = N - 1;
    out[i] = 1.f / (1.f + __expf(-h3[t]));
    if (both) out[nt + i] = y[t];
}

// ---------------- Launch ----------------

extern "C" void kernel_launch(void* const* d_in, const int* in_sizes, int n_in,
                              void* d_out, int out_size) {
    const float* x    = (const float*)d_in[0];
    const int*   ei   = (const int*)d_in[1];
    const float* y    = (const float*)d_in[2];
    const int*   tidx = (const int*)d_in[3];
    const float* W1l = (const float*)d_in[4];
    const float* W1r = (const float*)d_in[5];
    const float* a1  = (const float*)d_in[6];
    const float* b1  = (const float*)d_in[7];
    const float* W2l = (const float*)d_in[8];
    const float* W2r = (const float*)d_in[9];
    const float* a2  = (const float*)d_in[10];
    const float* b2  = (const float*)d_in[11];
    const float* W3l = (const float*)d_in[12];
    const float* W3r = (const float*)d_in[13];
    const float* a3  = (const float*)d_in[14];
    const float* b3  = (const float*)d_in[15];

    int N  = in_sizes[2];
    int E  = in_sizes[1] / 2;
    int NT = in_sizes[3];
    int IN = in_sizes[0] / N;

    const int* src = ei;
    const int* dst = ei + E;

    float *p_xl, *p_xr, *p_h, *p_logits;
    int *p_rowptr, *p_cursor, *p_deg, *p_csrsrc, *p_csrdst;
    cudaGetSymbolAddress((void**)&p_xl, g_xl);
    cudaGetSymbolAddress((void**)&p_xr, g_xr);
    cudaGetSymbolAddress((void**)&p_h,  g_h);
    cudaGetSymbolAddress((void**)&p_logits, g_logits);
    cudaGetSymbolAddress((void**)&p_rowptr, g_rowptr);
    cudaGetSymbolAddress((void**)&p_cursor, g_cursor);
    cudaGetSymbolAddress((void**)&p_deg,    g_deg);
    cudaGetSymbolAddress((void**)&p_csrsrc, g_csrsrc);
    cudaGetSymbolAddress((void**)&p_csrdst, g_csrdst);

    // ---- CSR build (kernel-only) ----
    zero_kernel<<<(N + 255) / 256, 256>>>(p_deg, N);
    hist_kernel<<<(E + 255) / 256, 256>>>(dst, E, N, p_deg);
    scan_kernel<<<1, 1024>>>(p_deg, p_rowptr, p_cursor, N);
    scatter_kernel<<<(E + 255) / 256, 256>>>(src, dst, E, N, p_cursor, p_csrsrc, p_csrdst);

    // ---- Layer 1: 129 -> 256 (H=2, C=128) ----
    {
        dim3 g((256 + BN - 1) / BN, (N + BM - 1) / BM);
        gemm_kernel<<<g, 256>>>(x, W1l, p_xl, N, IN, 256);
        gemm_kernel<<<g, 256>>>(x, W1r, p_xr, N, IN, 256);
        edge_logits_kernel<<<(E * 32 + 255) / 256, 256>>>(p_xl, p_xr, a1, p_csrsrc, p_csrdst, E, 2, 128, p_logits);
        agg_kernel<<<N, 256>>>(p_xl, p_logits, p_rowptr, p_csrsrc, b1, p_h, 128, 2);
    }

    // ---- Layer 2: 256 -> 128 (H=1, C=128) ----
    {
        dim3 g((128 + BN - 1) / BN, (N + BM - 1) / BM);
        gemm_kernel<<<g, 256>>>(p_h, W2l, p_xl, N, 256, 128);
        gemm_kernel<<<g, 256>>>(p_h, W2r, p_xr, N, 256, 128);
        edge_logits_kernel<<<(E * 32 + 255) / 256, 256>>>(p_xl, p_xr, a2, p_csrsrc, p_csrdst, E, 1, 128, p_logits);
        agg_kernel<<<N, 128>>>(p_xl, p_logits, p_rowptr, p_csrsrc, b2, p_h, 128, 1);
    }

    // ---- Layer 3: 128 -> 1 (H=1, C=1) ----
    {
        gemv_kernel<<<(N * 32 + 255) / 256, 256>>>(p_h, W3l, p_xl, N, 128);
        gemv_kernel<<<(N * 32 + 255) / 256, 256>>>(p_h, W3r, p_xr, N, 128);
        edge3_kernel<<<(E + 255) / 256, 256>>>(p_xl, p_xr, a3, p_csrsrc, p_csrdst, E, p_logits);
        agg3_kernel<<<(N + 255) / 256, 256>>>(p_xl, p_logits, p_rowptr, p_csrsrc, b3, p_h, N);
    }

    // ---- Output: pred[train_idx], y[train_idx] ----
    int both = (out_size >= 2 * NT) ? 1 : 0;
    gather_kernel<<<(NT + 255) / 256, 256>>>(p_h, y, tidx, NT, N, (float*)d_out, both);
}

// round 7
// speedup vs baseline: 1.2770x; 1.2770x over previous
#include <cuda_runtime.h>
#include <cuda_bf16.h>

// ---------------------------------------------------------------------------
// GATv2 GNN, 3 layers. CSR-by-dst; node-parallel softmax+agg.
// R4 (resubmit after infra failure): 128x128x8 SGEMM (8x8 microtile, fused l/r
// via blockIdx.z), float4 edge logits.
// ---------------------------------------------------------------------------

#define MAX_N 50000
#define MAX_E 800000

__device__ float g_xl[MAX_N * 256];
__device__ float g_xr[MAX_N * 256];
__device__ float g_h [MAX_N * 256];
__device__ float g_logits[MAX_E * 2];
__device__ int   g_rowptr[MAX_N + 1];
__device__ int   g_cursor[MAX_N];
__device__ int   g_deg   [MAX_N];
__device__ int   g_csrsrc[MAX_E];
__device__ int   g_csrdst[MAX_E];

// ---------------- CSR build ----------------

__global__ void zero_kernel(int* __restrict__ p, int n) {
    int i = blockIdx.x * blockDim.x + threadIdx.x;
    if (i < n) p[i] = 0;
}

__global__ void hist_kernel(const int* __restrict__ dst, int E, int N, int* __restrict__ deg) {
    int e = blockIdx.x * blockDim.x + threadIdx.x;
    if (e >= E) return;
    int d = dst[e];
    if (d >= 0 && d < N) atomicAdd(&deg[d], 1);
}

__global__ void scan_kernel(const int* __restrict__ deg, int* __restrict__ rowptr,
                            int* __restrict__ cursor, int n) {
    __shared__ int warp_s[32];
    __shared__ int s_carry;
    int lane = threadIdx.x & 31, wid = threadIdx.x >> 5;
    if (threadIdx.x == 0) s_carry = 0;
    __syncthreads();
    for (int base = 0; base < n; base += 1024) {
        int i = base + threadIdx.x;
        int v = (i < n) ? deg[i] : 0;
        int x = v;
        #pragma unroll
        for (int o = 1; o < 32; o <<= 1) { int t = __shfl_up_sync(0xffffffffu, x, o); if (lane >= o) x += t; }
        if (lane == 31) warp_s[wid] = x;
        __syncthreads();
        if (wid == 0) {
            int y = warp_s[lane];
            #pragma unroll
            for (int o = 1; o < 32; o <<= 1) { int t = __shfl_up_sync(0xffffffffu, y, o); if (lane >= o) y += t; }
            warp_s[lane] = y;
        }
        __syncthreads();
        int off = s_carry + (wid ? warp_s[wid - 1] : 0);
        if (i < n) {
            int excl = off + x - v;
            rowptr[i] = excl;
            cursor[i] = excl;
        }
        int total = warp_s[31];
        __syncthreads();
        if (threadIdx.x == 0) s_carry += total;
        __syncthreads();
    }
    if (threadIdx.x == 0) rowptr[n] = s_carry;
}

__global__ void scatter_kernel(const int* __restrict__ src, const int* __restrict__ dst,
                               int E, int N, int* __restrict__ cursor,
                               int* __restrict__ csrsrc, int* __restrict__ csrdst) {
    int e = blockIdx.x * blockDim.x + threadIdx.x;
    if (e >= E) return;
    int d = dst[e];
    if (d < 0 || d >= N) return;
    int s = src[e];
    int p = atomicAdd(&cursor[d], 1);
    csrsrc[p] = s;
    csrdst[p] = d;
}

// ---------------- SGEMM: 128x128 tile, BK=8, 8x8 strided microtile ----------------
// Computes C0 = A@B0 and (blockIdx.z==1) C1 = A@B1 in one launch.

#define GBM 128
#define GBN 128
#define GBK 8

__global__ __launch_bounds__(256) void gemm2_kernel(
    const float* __restrict__ A,
    const float* __restrict__ B0, const float* __restrict__ B1,
    float* __restrict__ C0, float* __restrict__ C1,
    int M, int K, int N) {
    const float* __restrict__ B = blockIdx.z ? B1 : B0;
    float* __restrict__ C = blockIdx.z ? C1 : C0;

    __shared__ float As[GBK][GBM];
    __shared__ float Bs[GBK][GBN];

    int tid = threadIdx.x;
    int tx = tid & 15, ty = tid >> 4;          // 16 x 16
    int m0 = blockIdx.y * GBM, n0 = blockIdx.x * GBN;

    // A loads: thread covers (m = tid>>1, k = (tid&1)*4 .. +3)
    int a_m = tid >> 1, a_k = (tid & 1) * 4;
    // B loads: thread covers (k = tid>>5, n = (tid&31)*4 .. +3)
    int b_k = tid >> 5, b_n = (tid & 31) * 4;

    float acc[8][8];
    #pragma unroll
    for (int i = 0; i < 8; i++)
        #pragma unroll
        for (int j = 0; j < 8; j++) acc[i][j] = 0.f;

    for (int k0 = 0; k0 < K; k0 += GBK) {
        int gm = m0 + a_m;
        #pragma unroll
        for (int j = 0; j < 4; j++) {
            int k = k0 + a_k + j;
            As[a_k + j][a_m] = (gm < M && k < K) ? A[(long)gm * K + k] : 0.f;
        }
        int gk = k0 + b_k;
        #pragma unroll
        for (int j = 0; j < 4; j++) {
            int n = n0 + b_n + j;
            Bs[b_k][b_n + j] = (gk < K && n < N) ? B[(long)gk * N + n] : 0.f;
        }
        __syncthreads();
        #pragma unroll
        for (int kk = 0; kk < GBK; kk++) {
            float a[8], b[8];
            #pragma unroll
            for (int i = 0; i < 8; i++) a[i] = As[kk][ty + i * 16];
            #pragma unroll
            for (int j = 0; j < 8; j++) b[j] = Bs[kk][tx + j * 16];
            #pragma unroll
            for (int i = 0; i < 8; i++)
                #pragma unroll
                for (int j = 0; j < 8; j++)
                    acc[i][j] = fmaf(a[i], b[j], acc[i][j]);
        }
        __syncthreads();
    }
    #pragma unroll
    for (int i = 0; i < 8; i++) {
        int m = m0 + ty + i * 16;
        if (m >= M) continue;
        #pragma unroll
        for (int j = 0; j < 8; j++) {
            int n = n0 + tx + j * 16;
            if (n < N) C[(long)m * N + n] = acc[i][j];
        }
    }
}

// GEMV: out[m] = dot(A[m,:K], w[:K]), K multiple of 128, float4.
__global__ void gemv_kernel(const float* __restrict__ A, const float* __restrict__ w,
                            float* __restrict__ out, int M, int K) {
    int gt = blockIdx.x * blockDim.x + threadIdx.x;
    int row = gt >> 5, lane = gt & 31;
    if (row >= M) return;
    const float4* a4 = (const float4*)(A + (long)row * K);
    const float4* w4 = (const float4*)w;
    int K4 = K >> 2;
    float s = 0.f;
    for (int k = lane; k < K4; k += 32) {
        float4 a = a4[k], b = w4[k];
        s = fmaf(a.x, b.x, s); s = fmaf(a.y, b.y, s);
        s = fmaf(a.z, b.z, s); s = fmaf(a.w, b.w, s);
    }
    #pragma unroll
    for (int o = 16; o; o >>= 1) s += __shfl_xor_sync(0xffffffffu, s, o);
    if (lane == 0) out[row] = s;
}

// ---------------- Edge logits: warp per edge, C=128 via float4 ----------------

__global__ void edge_logits_kernel(const float* __restrict__ xl, const float* __restrict__ xr,
                                   const float* __restrict__ att,
                                   const int* __restrict__ csrsrc, const int* __restrict__ csrdst,
                                   int E, int H, float* __restrict__ logits) {
    int gt = blockIdx.x * blockDim.x + threadIdx.x;
    int e = gt >> 5, lane = gt & 31;
    if (e >= E) return;
    int s = csrsrc[e], d = csrdst[e];
    int HC4 = H * 32;                         // C=128 -> 32 float4 per head
    const float4* ps = (const float4*)xl + (long)s * HC4;
    const float4* pd = (const float4*)xr + (long)d * HC4;
    const float4* at = (const float4*)att;
    for (int h = 0; h < H; h++) {
        float4 va = ps[h * 32 + lane];
        float4 vb = pd[h * 32 + lane];
        float4 aa = at[h * 32 + lane];
        float vx = va.x + vb.x; vx = vx > 0.f ? vx : 0.2f * vx;
        float vy = va.y + vb.y; vy = vy > 0.f ? vy : 0.2f * vy;
        float vz = va.z + vb.z; vz = vz > 0.f ? vz : 0.2f * vz;
        float vw = va.w + vb.w; vw = vw > 0.f ? vw : 0.2f * vw;
        float acc = vx * aa.x + vy * aa.y + vz * aa.z + vw * aa.w;
        #pragma unroll
        for (int o = 16; o; o >>= 1) acc += __shfl_xor_sync(0xffffffffu, acc, o);
        if (lane == 0) logits[(long)e * H + h] = acc;
    }
}

__global__ void edge3_kernel(const float* __restrict__ xl, const float* __restrict__ xr,
                             const float* __restrict__ att,
                             const int* __restrict__ csrsrc, const int* __restrict__ csrdst,
                             int E, float* __restrict__ logits) {
    int e = blockIdx.x * blockDim.x + threadIdx.x;
    if (e >= E) return;
    float v = xl[csrsrc[e]] + xr[csrdst[e]];
    v = v > 0.f ? v : 0.2f * v;
    logits[e] = v * att[0];
}

// ---------------- Node-parallel softmax + mean aggregate ----------------

__global__ void agg_kernel(const float* __restrict__ xl, const float* __restrict__ logits,
                           const int* __restrict__ rowptr, const int* __restrict__ csrsrc,
                           const float* __restrict__ bias, float* __restrict__ out,
                           int C, int H) {
    int node = blockIdx.x;
    int tid = threadIdx.x;           // H*C threads
    int HC = H * C;
    int h = tid / C;
    int beg = rowptr[node], end = rowptr[node + 1];
    long obase = (long)node * HC + tid;
    if (beg == end) { out[obase] = bias[tid]; return; }
    float m = -1e30f;
    for (int e = beg; e < end; e++) m = fmaxf(m, logits[(long)e * H + h]);
    float s = 0.f, acc = 0.f;
    for (int e = beg; e < end; e++) {
        float w = __expf(logits[(long)e * H + h] - m);
        s += w;
        acc = fmaf(w, xl[(long)csrsrc[e] * HC + tid], acc);
    }
    float deg = (float)(end - beg);
    out[obase] = acc / (s * deg) + bias[tid];
}

__global__ void agg3_kernel(const float* __restrict__ xl, const float* __restrict__ logits,
                            const int* __restrict__ rowptr, const int* __restrict__ csrsrc,
                            const float* __restrict__ bias, float* __restrict__ out, int N) {
    int node = blockIdx.x * blockDim.x + threadIdx.x;
    if (node >= N) return;
    int beg = rowptr[node], end = rowptr[node + 1];
    if (beg == end) { out[node] = bias[0]; return; }
    float m = -1e30f;
    for (int e = beg; e < end; e++) m = fmaxf(m, logits[e]);
    float s = 0.f, acc = 0.f;
    for (int e = beg; e < end; e++) {
        float w = __expf(logits[e] - m);
        s += w;
        acc = fmaf(w, xl[csrsrc[e]], acc);
    }
    out[node] = acc / (s * (float)(end - beg)) + bias[0];
}

// ---------------- Output gather ----------------

__global__ void gather_kernel(const float* __restrict__ h3, const float* __restrict__ y,
                              const int* __restrict__ tidx, int nt, int N,
                              float* __restrict__ out, int both) {
    int i = blockIdx.x * blockDim.x + threadIdx.x;
    if (i >= nt) return;
    int t = tidx[i];
    if (t < 0) t = 0;
    if (t >= N) t = N - 1;
    out[i] = 1.f / (1.f + __expf(-h3[t]));
    if (both) out[nt + i] = y[t];
}

// ---------------- Launch ----------------

extern "C" void kernel_launch(void* const* d_in, const int* in_sizes, int n_in,
                              void* d_out, int out_size) {
    const float* x    = (const float*)d_in[0];
    const int*   ei   = (const int*)d_in[1];
    const float* y    = (const float*)d_in[2];
    const int*   tidx = (const int*)d_in[3];
    const float* W1l = (const float*)d_in[4];
    const float* W1r = (const float*)d_in[5];
    const float* a1  = (const float*)d_in[6];
    const float* b1  = (const float*)d_in[7];
    const float* W2l = (const float*)d_in[8];
    const float* W2r = (const float*)d_in[9];
    const float* a2  = (const float*)d_in[10];
    const float* b2  = (const float*)d_in[11];
    const float* W3l = (const float*)d_in[12];
    const float* W3r = (const float*)d_in[13];
    const float* a3  = (const float*)d_in[14];
    const float* b3  = (const float*)d_in[15];

    int N  = in_sizes[2];
    int E  = in_sizes[1] / 2;
    int NT = in_sizes[3];
    int IN = in_sizes[0] / N;

    const int* src = ei;
    const int* dst = ei + E;

    float *p_xl, *p_xr, *p_h, *p_logits;
    int *p_rowptr, *p_cursor, *p_deg, *p_csrsrc, *p_csrdst;
    cudaGetSymbolAddress((void**)&p_xl, g_xl);
    cudaGetSymbolAddress((void**)&p_xr, g_xr);
    cudaGetSymbolAddress((void**)&p_h,  g_h);
    cudaGetSymbolAddress((void**)&p_logits, g_logits);
    cudaGetSymbolAddress((void**)&p_rowptr, g_rowptr);
    cudaGetSymbolAddress((void**)&p_cursor, g_cursor);
    cudaGetSymbolAddress((void**)&p_deg,    g_deg);
    cudaGetSymbolAddress((void**)&p_csrsrc, g_csrsrc);
    cudaGetSymbolAddress((void**)&p_csrdst, g_csrdst);

    // ---- CSR build (kernel-only) ----
    zero_kernel<<<(N + 255) / 256, 256>>>(p_deg, N);
    hist_kernel<<<(E + 255) / 256, 256>>>(dst, E, N, p_deg);
    scan_kernel<<<1, 1024>>>(p_deg, p_rowptr, p_cursor, N);
    scatter_kernel<<<(E + 255) / 256, 256>>>(src, dst, E, N, p_cursor, p_csrsrc, p_csrdst);

    // ---- Layer 1: 129 -> 256 (H=2, C=128) ----
    {
        dim3 g((256 + GBN - 1) / GBN, (N + GBM - 1) / GBM, 2);
        gemm2_kernel<<<g, 256>>>(x, W1l, W1r, p_xl, p_xr, N, IN, 256);
        edge_logits_kernel<<<(E * 32 + 255) / 256, 256>>>(p_xl, p_xr, a1, p_csrsrc, p_csrdst, E, 2, p_logits);
        agg_kernel<<<N, 256>>>(p_xl, p_logits, p_rowptr, p_csrsrc, b1, p_h, 128, 2);
    }

    // ---- Layer 2: 256 -> 128 (H=1, C=128) ----
    {
        dim3 g((128 + GBN - 1) / GBN, (N + GBM - 1) / GBM, 2);
        gemm2_kernel<<<g, 256>>>(p_h, W2l, W2r, p_xl, p_xr, N, 256, 128);
        edge_logits_kernel<<<(E * 32 + 255) / 256, 256>>>(p_xl, p_xr, a2, p_csrsrc, p_csrdst, E, 1, p_logits);
        agg_kernel<<<N, 128>>>(p_xl, p_logits, p_rowptr, p_csrsrc, b2, p_h, 128, 1);
    }

    // ---- Layer 3: 128 -> 1 (H=1, C=1) ----
    {
        gemv_kernel<<<(N * 32 + 255) / 256, 256>>>(p_h, W3l, p_xl, N, 128);
        gemv_kernel<<<(N * 32 + 255) / 256, 256>>>(p_h, W3r, p_xr, N, 128);
        edge3_kernel<<<(E + 255) / 256, 256>>>(p_xl, p_xr, a3, p_csrsrc, p_csrdst, E, p_logits);
        agg3_kernel<<<(N + 255) / 256, 256>>>(p_xl, p_logits, p_rowptr, p_csrsrc, b3, p_h, N);
    }

    // ---- Output: pred[train_idx], y[train_idx] ----
    int both = (out_size >= 2 * NT) ? 1 : 0;
    gather_kernel<<<(NT + 255) / 256, 256>>>(p_h, y, tidx, NT, N, (float*)d_out, both);
}

// round 8
// speedup vs baseline: 2.3562x; 1.8451x over previous
#include <cuda_runtime.h>
#include <cuda_bf16.h>
#include <cstdint>

// ---------------------------------------------------------------------------
// GATv2 GNN, 3 layers. CSR-by-dst; node-parallel softmax+agg.
// R8: tf32 mma.sync GEMM (128x128x16, 8 warps), float4 agg (thread = 4 channels).
// ---------------------------------------------------------------------------

#define MAX_N 50000
#define MAX_E 800000

__device__ float g_xl[MAX_N * 256];
__device__ float g_xr[MAX_N * 256];
__device__ float g_h [MAX_N * 256];
__device__ float g_logits[MAX_E * 2];
__device__ int   g_rowptr[MAX_N + 1];
__device__ int   g_cursor[MAX_N];
__device__ int   g_deg   [MAX_N];
__device__ int   g_csrsrc[MAX_E];
__device__ int   g_csrdst[MAX_E];

// ---------------- CSR build ----------------

__global__ void zero_kernel(int* __restrict__ p, int n) {
    int i = blockIdx.x * blockDim.x + threadIdx.x;
    if (i < n) p[i] = 0;
}

__global__ void hist_kernel(const int* __restrict__ dst, int E, int N, int* __restrict__ deg) {
    int e = blockIdx.x * blockDim.x + threadIdx.x;
    if (e >= E) return;
    int d = dst[e];
    if (d >= 0 && d < N) atomicAdd(&deg[d], 1);
}

__global__ void scan_kernel(const int* __restrict__ deg, int* __restrict__ rowptr,
                            int* __restrict__ cursor, int n) {
    __shared__ int warp_s[32];
    __shared__ int s_carry;
    int lane = threadIdx.x & 31, wid = threadIdx.x >> 5;
    if (threadIdx.x == 0) s_carry = 0;
    __syncthreads();
    for (int base = 0; base < n; base += 1024) {
        int i = base + threadIdx.x;
        int v = (i < n) ? deg[i] : 0;
        int x = v;
        #pragma unroll
        for (int o = 1; o < 32; o <<= 1) { int t = __shfl_up_sync(0xffffffffu, x, o); if (lane >= o) x += t; }
        if (lane == 31) warp_s[wid] = x;
        __syncthreads();
        if (wid == 0) {
            int y = warp_s[lane];
            #pragma unroll
            for (int o = 1; o < 32; o <<= 1) { int t = __shfl_up_sync(0xffffffffu, y, o); if (lane >= o) y += t; }
            warp_s[lane] = y;
        }
        __syncthreads();
        int off = s_carry + (wid ? warp_s[wid - 1] : 0);
        if (i < n) {
            int excl = off + x - v;
            rowptr[i] = excl;
            cursor[i] = excl;
        }
        int total = warp_s[31];
        __syncthreads();
        if (threadIdx.x == 0) s_carry += total;
        __syncthreads();
    }
    if (threadIdx.x == 0) rowptr[n] = s_carry;
}

__global__ void scatter_kernel(const int* __restrict__ src, const int* __restrict__ dst,
                               int E, int N, int* __restrict__ cursor,
                               int* __restrict__ csrsrc, int* __restrict__ csrdst) {
    int e = blockIdx.x * blockDim.x + threadIdx.x;
    if (e >= E) return;
    int d = dst[e];
    if (d < 0 || d >= N) return;
    int s = src[e];
    int p = atomicAdd(&cursor[d], 1);
    csrsrc[p] = s;
    csrdst[p] = d;
}

// ---------------- tf32 tensor-core GEMM: 128x128x16, 8 warps of 32x64 ----------------
// C0 = A@B0, (blockIdx.z==1) C1 = A@B1.  A:[M,K] row-major, B:[K,N] row-major.
// N must be a multiple of 128 (true: 256, 128).

#define TBM 128
#define TBN 128
#define TBK 16
#define TPAD 136   // smem row stride (floats): bank map (8k+g) conflict-free

__device__ __forceinline__ uint32_t f2tf32(float v) {
    uint32_t t;
    asm("cvt.rna.tf32.f32 %0, %1;" : "=r"(t) : "f"(v));
    return t;
}

__global__ __launch_bounds__(256) void gemm_tf32_kernel(
    const float* __restrict__ A,
    const float* __restrict__ B0, const float* __restrict__ B1,
    float* __restrict__ C0, float* __restrict__ C1,
    int M, int K, int N) {
    const float* __restrict__ B = blockIdx.z ? B1 : B0;
    float* __restrict__ C = blockIdx.z ? C1 : C0;

    __shared__ float As[TBK][TPAD];
    __shared__ float Bs[TBK][TPAD];

    int tid = threadIdx.x;
    int wid = tid >> 5, lane = tid & 31;
    int m0 = blockIdx.y * TBM, n0 = blockIdx.x * TBN;
    int warp_m = (wid >> 1) << 5;   // 0,32,64,96
    int warp_n = (wid & 1) << 6;    // 0,64

    float c[2][8][4];
    #pragma unroll
    for (int i = 0; i < 2; i++)
        #pragma unroll
        for (int j = 0; j < 8; j++)
            #pragma unroll
            for (int q = 0; q < 4; q++) c[i][j][q] = 0.f;

    // A loads: k = tid&15, rows m = (tid>>4) + 16*i
    int ak = tid & 15, am = tid >> 4;
    // B loads: k = tid>>4, float4 quad = tid&15 (and +16)
    int bk = tid >> 4, bq = tid & 15;

    int r = lane & 3, g = lane >> 2;

    for (int k0 = 0; k0 < K; k0 += TBK) {
        bool kokA = (k0 + ak) < K;
        #pragma unroll
        for (int i = 0; i < 8; i++) {
            int m = am + (i << 4);
            float v = (kokA && (m0 + m) < M) ? A[(long)(m0 + m) * K + k0 + ak] : 0.f;
            As[ak][m] = __uint_as_float(f2tf32(v));
        }
        {
            bool kokB = (k0 + bk) < K;
            float4 v0 = make_float4(0.f, 0.f, 0.f, 0.f), v1 = v0;
            if (kokB) {
                const float4* Brow = (const float4*)(B + (long)(k0 + bk) * N + n0);
                v0 = Brow[bq];
                v1 = Brow[bq + 16];
            }
            v0.x = __uint_as_float(f2tf32(v0.x)); v0.y = __uint_as_float(f2tf32(v0.y));
            v0.z = __uint_as_float(f2tf32(v0.z)); v0.w = __uint_as_float(f2tf32(v0.w));
            v1.x = __uint_as_float(f2tf32(v1.x)); v1.y = __uint_as_float(f2tf32(v1.y));
            v1.z = __uint_as_float(f2tf32(v1.z)); v1.w = __uint_as_float(f2tf32(v1.w));
            *(float4*)&Bs[bk][bq << 2] = v0;
            *(float4*)&Bs[bk][64 + (bq << 2)] = v1;
        }
        __syncthreads();

        #pragma unroll
        for (int kk = 0; kk < TBK; kk += 8) {
            uint32_t a[2][4], b[8][2];
            #pragma unroll
            for (int i = 0; i < 2; i++) {
                int mb = warp_m + (i << 4);
                a[i][0] = __float_as_uint(As[kk + r][mb + g]);
                a[i][1] = __float_as_uint(As[kk + r][mb + g + 8]);
                a[i][2] = __float_as_uint(As[kk + r + 4][mb + g]);
                a[i][3] = __float_as_uint(As[kk + r + 4][mb + g + 8]);
            }
            #pragma unroll
            for (int j = 0; j < 8; j++) {
                int nb = warp_n + (j << 3);
                b[j][0] = __float_as_uint(Bs[kk + r][nb + g]);
                b[j][1] = __float_as_uint(Bs[kk + r + 4][nb + g]);
            }
            #pragma unroll
            for (int i = 0; i < 2; i++)
                #pragma unroll
                for (int j = 0; j < 8; j++)
                    asm volatile(
                        "mma.sync.aligned.m16n8k8.row.col.f32.tf32.tf32.f32 "
                        "{%0,%1,%2,%3}, {%4,%5,%6,%7}, {%8,%9}, {%0,%1,%2,%3};"
                        : "+f"(c[i][j][0]), "+f"(c[i][j][1]), "+f"(c[i][j][2]), "+f"(c[i][j][3])
                        : "r"(a[i][0]), "r"(a[i][1]), "r"(a[i][2]), "r"(a[i][3]),
                          "r"(b[j][0]), "r"(b[j][1]));
        }
        __syncthreads();
    }

    // Epilogue
    #pragma unroll
    for (int i = 0; i < 2; i++) {
        #pragma unroll
        for (int j = 0; j < 8; j++) {
            int col = n0 + warp_n + (j << 3) + (r << 1);
            int row0 = m0 + warp_m + (i << 4) + g;
            if (row0 < M) {
                C[(long)row0 * N + col]     = c[i][j][0];
                C[(long)row0 * N + col + 1] = c[i][j][1];
            }
            int row1 = row0 + 8;
            if (row1 < M) {
                C[(long)row1 * N + col]     = c[i][j][2];
                C[(long)row1 * N + col + 1] = c[i][j][3];
            }
        }
    }
}

// GEMV: out[m] = dot(A[m,:K], w[:K]), K multiple of 128, float4.
__global__ void gemv_kernel(const float* __restrict__ A, const float* __restrict__ w,
                            float* __restrict__ out, int M, int K) {
    int gt = blockIdx.x * blockDim.x + threadIdx.x;
    int row = gt >> 5, lane = gt & 31;
    if (row >= M) return;
    const float4* a4 = (const float4*)(A + (long)row * K);
    const float4* w4 = (const float4*)w;
    int K4 = K >> 2;
    float s = 0.f;
    for (int k = lane; k < K4; k += 32) {
        float4 a = a4[k], b = w4[k];
        s = fmaf(a.x, b.x, s); s = fmaf(a.y, b.y, s);
        s = fmaf(a.z, b.z, s); s = fmaf(a.w, b.w, s);
    }
    #pragma unroll
    for (int o = 16; o; o >>= 1) s += __shfl_xor_sync(0xffffffffu, s, o);
    if (lane == 0) out[row] = s;
}

// ---------------- Edge logits: warp per edge, C=128 via float4 ----------------

__global__ void edge_logits_kernel(const float* __restrict__ xl, const float* __restrict__ xr,
                                   const float* __restrict__ att,
                                   const int* __restrict__ csrsrc, const int* __restrict__ csrdst,
                                   int E, int H, float* __restrict__ logits) {
    int gt = blockIdx.x * blockDim.x + threadIdx.x;
    int e = gt >> 5, lane = gt & 31;
    if (e >= E) return;
    int s = csrsrc[e], d = csrdst[e];
    int HC4 = H * 32;                         // C=128 -> 32 float4 per head
    const float4* ps = (const float4*)xl + (long)s * HC4;
    const float4* pd = (const float4*)xr + (long)d * HC4;
    const float4* at = (const float4*)att;
    for (int h = 0; h < H; h++) {
        float4 va = ps[h * 32 + lane];
        float4 vb = pd[h * 32 + lane];
        float4 aa = at[h * 32 + lane];
        float vx = va.x + vb.x; vx = vx > 0.f ? vx : 0.2f * vx;
        float vy = va.y + vb.y; vy = vy > 0.f ? vy : 0.2f * vy;
        float vz = va.z + vb.z; vz = vz > 0.f ? vz : 0.2f * vz;
        float vw = va.w + vb.w; vw = vw > 0.f ? vw : 0.2f * vw;
        float acc = vx * aa.x + vy * aa.y + vz * aa.z + vw * aa.w;
        #pragma unroll
        for (int o = 16; o; o >>= 1) acc += __shfl_xor_sync(0xffffffffu, acc, o);
        if (lane == 0) logits[(long)e * H + h] = acc;
    }
}

__global__ void edge3_kernel(const float* __restrict__ xl, const float* __restrict__ xr,
                             const float* __restrict__ att,
                             const int* __restrict__ csrsrc, const int* __restrict__ csrdst,
                             int E, float* __restrict__ logits) {
    int e = blockIdx.x * blockDim.x + threadIdx.x;
    if (e >= E) return;
    float v = xl[csrsrc[e]] + xr[csrdst[e]];
    v = v > 0.f ? v : 0.2f * v;
    logits[e] = v * att[0];
}

// ---------------- Node-parallel softmax + mean aggregate (float4 per thread) ----------
// Thread handles 4 channels. tpn = HC/4 threads per node; 256/tpn nodes per block.

__global__ __launch_bounds__(256) void agg4_kernel(
    const float* __restrict__ xl, const float* __restrict__ logits,
    const int* __restrict__ rowptr, const int* __restrict__ csrsrc,
    const float* __restrict__ bias, float* __restrict__ out,
    int N, int H, int C) {
    int HC = H * C;
    int tpn = HC >> 2;
    int npb = 256 / tpn;
    int node = blockIdx.x * npb + threadIdx.x / tpn;
    int q = threadIdx.x % tpn;          // channel-quad index
    if (node >= N) return;
    int h = (q << 2) / C;

    const float4* xl4 = (const float4*)xl;
    const float4* b4  = (const float4*)bias;
    float4* out4 = (float4*)out;

    int beg = rowptr[node], end = rowptr[node + 1];
    long obase = (long)node * tpn + q;
    if (beg == end) { out4[obase] = b4[q]; return; }

    float m = -1e30f;
    for (int e = beg; e < end; e++) m = fmaxf(m, logits[(long)e * H + h]);

    float s = 0.f;
    float4 acc = make_float4(0.f, 0.f, 0.f, 0.f);
    for (int e = beg; e < end; e++) {
        float w = __expf(logits[(long)e * H + h] - m);
        s += w;
        float4 v = xl4[(long)csrsrc[e] * tpn + q];
        acc.x = fmaf(w, v.x, acc.x);
        acc.y = fmaf(w, v.y, acc.y);
        acc.z = fmaf(w, v.z, acc.z);
        acc.w = fmaf(w, v.w, acc.w);
    }
    float inv = 1.f / (s * (float)(end - beg));
    float4 bb = b4[q];
    float4 o;
    o.x = acc.x * inv + bb.x;
    o.y = acc.y * inv + bb.y;
    o.z = acc.z * inv + bb.z;
    o.w = acc.w * inv + bb.w;
    out4[obase] = o;
}

__global__ void agg3_kernel(const float* __restrict__ xl, const float* __restrict__ logits,
                            const int* __restrict__ rowptr, const int* __restrict__ csrsrc,
                            const float* __restrict__ bias, float* __restrict__ out, int N) {
    int node = blockIdx.x * blockDim.x + threadIdx.x;
    if (node >= N) return;
    int beg = rowptr[node], end = rowptr[node + 1];
    if (beg == end) { out[node] = bias[0]; return; }
    float m = -1e30f;
    for (int e = beg; e < end; e++) m = fmaxf(m, logits[e]);
    float s = 0.f, acc = 0.f;
    for (int e = beg; e < end; e++) {
        float w = __expf(logits[e] - m);
        s += w;
        acc = fmaf(w, xl[csrsrc[e]], acc);
    }
    out[node] = acc / (s * (float)(end - beg)) + bias[0];
}

// ---------------- Output gather ----------------

__global__ void gather_kernel(const float* __restrict__ h3, const float* __restrict__ y,
                              const int* __restrict__ tidx, int nt, int N,
                              float* __restrict__ out, int both) {
    int i = blockIdx.x * blockDim.x + threadIdx.x;
    if (i >= nt) return;
    int t = tidx[i];
    if (t < 0) t = 0;
    if (t >= N) t = N - 1;
    out[i] = 1.f / (1.f + __expf(-h3[t]));
    if (both) out[nt + i] = y[t];
}

// ---------------- Launch ----------------

extern "C" void kernel_launch(void* const* d_in, const int* in_sizes, int n_in,
                              void* d_out, int out_size) {
    const float* x    = (const float*)d_in[0];
    const int*   ei   = (const int*)d_in[1];
    const float* y    = (const float*)d_in[2];
    const int*   tidx = (const int*)d_in[3];
    const float* W1l = (const float*)d_in[4];
    const float* W1r = (const float*)d_in[5];
    const float* a1  = (const float*)d_in[6];
    const float* b1  = (const float*)d_in[7];
    const float* W2l = (const float*)d_in[8];
    const float* W2r = (const float*)d_in[9];
    const float* a2  = (const float*)d_in[10];
    const float* b2  = (const float*)d_in[11];
    const float* W3l = (const float*)d_in[12];
    const float* W3r = (const float*)d_in[13];
    const float* a3  = (const float*)d_in[14];
    const float* b3  = (const float*)d_in[15];

    int N  = in_sizes[2];
    int E  = in_sizes[1] / 2;
    int NT = in_sizes[3];
    int IN = in_sizes[0] / N;

    const int* src = ei;
    const int* dst = ei + E;

    float *p_xl, *p_xr, *p_h, *p_logits;
    int *p_rowptr, *p_cursor, *p_deg, *p_csrsrc, *p_csrdst;
    cudaGetSymbolAddress((void**)&p_xl, g_xl);
    cudaGetSymbolAddress((void**)&p_xr, g_xr);
    cudaGetSymbolAddress((void**)&p_h,  g_h);
    cudaGetSymbolAddress((void**)&p_logits, g_logits);
    cudaGetSymbolAddress((void**)&p_rowptr, g_rowptr);
    cudaGetSymbolAddress((void**)&p_cursor, g_cursor);
    cudaGetSymbolAddress((void**)&p_deg,    g_deg);
    cudaGetSymbolAddress((void**)&p_csrsrc, g_csrsrc);
    cudaGetSymbolAddress((void**)&p_csrdst, g_csrdst);

    // ---- CSR build (kernel-only) ----
    zero_kernel<<<(N + 255) / 256, 256>>>(p_deg, N);
    hist_kernel<<<(E + 255) / 256, 256>>>(dst, E, N, p_deg);
    scan_kernel<<<1, 1024>>>(p_deg, p_rowptr, p_cursor, N);
    scatter_kernel<<<(E + 255) / 256, 256>>>(src, dst, E, N, p_cursor, p_csrsrc, p_csrdst);

    int gm = (N + TBM - 1) / TBM;

    // ---- Layer 1: 129 -> 256 (H=2, C=128) ----
    {
        dim3 g(256 / TBN, gm, 2);
        gemm_tf32_kernel<<<g, 256>>>(x, W1l, W1r, p_xl, p_xr, N, IN, 256);
        edge_logits_kernel<<<(E * 32 + 255) / 256, 256>>>(p_xl, p_xr, a1, p_csrsrc, p_csrdst, E, 2, p_logits);
        agg4_kernel<<<(N + 3) / 4, 256>>>(p_xl, p_logits, p_rowptr, p_csrsrc, b1, p_h, N, 2, 128);
    }

    // ---- Layer 2: 256 -> 128 (H=1, C=128) ----
    {
        dim3 g(128 / TBN, gm, 2);
        gemm_tf32_kernel<<<g, 256>>>(p_h, W2l, W2r, p_xl, p_xr, N, 256, 128);
        edge_logits_kernel<<<(E * 32 + 255) / 256, 256>>>(p_xl, p_xr, a2, p_csrsrc, p_csrdst, E, 1, p_logits);
        agg4_kernel<<<(N + 7) / 8, 256>>>(p_xl, p_logits, p_rowptr, p_csrsrc, b2, p_h, N, 1, 128);
    }

    // ---- Layer 3: 128 -> 1 (H=1, C=1) ----
    {
        gemv_kernel<<<(N * 32 + 255) / 256, 256>>>(p_h, W3l, p_xl, N, 128);
        gemv_kernel<<<(N * 32 + 255) / 256, 256>>>(p_h, W3r, p_xr, N, 128);
        edge3_kernel<<<(E + 255) / 256, 256>>>(p_xl, p_xr, a3, p_csrsrc, p_csrdst, E, p_logits);
        agg3_kernel<<<(N + 255) / 256, 256>>>(p_xl, p_logits, p_rowptr, p_csrsrc, b3, p_h, N);
    }

    // ---- Output: pred[train_idx], y[train_idx] ----
    int both = (out_size >= 2 * NT) ? 1 : 0;
    gather_kernel<<<(NT + 255) / 256, 256>>>(p_h, y, tidx, NT, N, (float*)d_out, both);
}

// round 13
// speedup vs baseline: 3.3176x; 1.4080x over previous
#include <cuda_runtime.h>
#include <cuda_bf16.h>
#include <cstdint>

// ---------------------------------------------------------------------------
// GATv2 GNN, 3 layers. CSR-by-dst; warp-per-node FUSED logits+softmax+aggregate
// (online softmax, single pass over edges). tf32 mma.sync GEMMs.
// R12: R9 fusion, template manually instantiated (infra de-risk), else identical.
// ---------------------------------------------------------------------------

#define MAX_N 50000
#define MAX_E 800000

__device__ float g_xl[MAX_N * 256];
__device__ float g_xr[MAX_N * 256];
__device__ float g_h [MAX_N * 256];
__device__ int   g_rowptr[MAX_N + 1];
__device__ int   g_cursor[MAX_N];
__device__ int   g_deg   [MAX_N];
__device__ int   g_csrsrc[MAX_E];

// ---------------- CSR build ----------------

__global__ void zero_kernel(int* __restrict__ p, int n) {
    int i = blockIdx.x * blockDim.x + threadIdx.x;
    if (i < n) p[i] = 0;
}

__global__ void hist_kernel(const int* __restrict__ dst, int E, int N, int* __restrict__ deg) {
    int e = blockIdx.x * blockDim.x + threadIdx.x;
    if (e >= E) return;
    int d = dst[e];
    if (d >= 0 && d < N) atomicAdd(&deg[d], 1);
}

__global__ void scan_kernel(const int* __restrict__ deg, int* __restrict__ rowptr,
                            int* __restrict__ cursor, int n) {
    __shared__ int warp_s[32];
    __shared__ int s_carry;
    int lane = threadIdx.x & 31, wid = threadIdx.x >> 5;
    if (threadIdx.x == 0) s_carry = 0;
    __syncthreads();
    for (int base = 0; base < n; base += 1024) {
        int i = base + threadIdx.x;
        int v = (i < n) ? deg[i] : 0;
        int x = v;
        #pragma unroll
        for (int o = 1; o < 32; o <<= 1) { int t = __shfl_up_sync(0xffffffffu, x, o); if (lane >= o) x += t; }
        if (lane == 31) warp_s[wid] = x;
        __syncthreads();
        if (wid == 0) {
            int y = warp_s[lane];
            #pragma unroll
            for (int o = 1; o < 32; o <<= 1) { int t = __shfl_up_sync(0xffffffffu, y, o); if (lane >= o) y += t; }
            warp_s[lane] = y;
        }
        __syncthreads();
        int off = s_carry + (wid ? warp_s[wid - 1] : 0);
        if (i < n) {
            int excl = off + x - v;
            rowptr[i] = excl;
            cursor[i] = excl;
        }
        int total = warp_s[31];
        __syncthreads();
        if (threadIdx.x == 0) s_carry += total;
        __syncthreads();
    }
    if (threadIdx.x == 0) rowptr[n] = s_carry;
}

__global__ void scatter_kernel(const int* __restrict__ src, const int* __restrict__ dst,
                               int E, int N, int* __restrict__ cursor,
                               int* __restrict__ csrsrc) {
    int e = blockIdx.x * blockDim.x + threadIdx.x;
    if (e >= E) return;
    int d = dst[e];
    if (d < 0 || d >= N) return;
    int s = src[e];
    int p = atomicAdd(&cursor[d], 1);
    csrsrc[p] = s;
}

// ---------------- tf32 tensor-core GEMM: 128x128x16, 8 warps of 32x64 ----------------

#define TBM 128
#define TBN 128
#define TBK 16
#define TPAD 136

__device__ __forceinline__ uint32_t f2tf32(float v) {
    uint32_t t;
    asm("cvt.rna.tf32.f32 %0, %1;" : "=r"(t) : "f"(v));
    return t;
}

__global__ __launch_bounds__(256) void gemm_tf32_kernel(
    const float* __restrict__ A,
    const float* __restrict__ B0, const float* __restrict__ B1,
    float* __restrict__ C0, float* __restrict__ C1,
    int M, int K, int N) {
    const float* __restrict__ B = blockIdx.z ? B1 : B0;
    float* __restrict__ C = blockIdx.z ? C1 : C0;

    __shared__ float As[TBK][TPAD];
    __shared__ float Bs[TBK][TPAD];

    int tid = threadIdx.x;
    int wid = tid >> 5, lane = tid & 31;
    int m0 = blockIdx.y * TBM, n0 = blockIdx.x * TBN;
    int warp_m = (wid >> 1) << 5;
    int warp_n = (wid & 1) << 6;

    float c[2][8][4];
    #pragma unroll
    for (int i = 0; i < 2; i++)
        #pragma unroll
        for (int j = 0; j < 8; j++)
            #pragma unroll
            for (int q = 0; q < 4; q++) c[i][j][q] = 0.f;

    int ak = tid & 15, am = tid >> 4;
    int bk = tid >> 4, bq = tid & 15;
    int r = lane & 3, g = lane >> 2;

    for (int k0 = 0; k0 < K; k0 += TBK) {
        bool kokA = (k0 + ak) < K;
        #pragma unroll
        for (int i = 0; i < 8; i++) {
            int m = am + (i << 4);
            float v = (kokA && (m0 + m) < M) ? A[(long)(m0 + m) * K + k0 + ak] : 0.f;
            As[ak][m] = __uint_as_float(f2tf32(v));
        }
        {
            bool kokB = (k0 + bk) < K;
            float4 v0 = make_float4(0.f, 0.f, 0.f, 0.f), v1 = v0;
            if (kokB) {
                const float4* Brow = (const float4*)(B + (long)(k0 + bk) * N + n0);
                v0 = Brow[bq];
                v1 = Brow[bq + 16];
            }
            v0.x = __uint_as_float(f2tf32(v0.x)); v0.y = __uint_as_float(f2tf32(v0.y));
            v0.z = __uint_as_float(f2tf32(v0.z)); v0.w = __uint_as_float(f2tf32(v0.w));
            v1.x = __uint_as_float(f2tf32(v1.x)); v1.y = __uint_as_float(f2tf32(v1.y));
            v1.z = __uint_as_float(f2tf32(v1.z)); v1.w = __uint_as_float(f2tf32(v1.w));
            *(float4*)&Bs[bk][bq << 2] = v0;
            *(float4*)&Bs[bk][64 + (bq << 2)] = v1;
        }
        __syncthreads();

        #pragma unroll
        for (int kk = 0; kk < TBK; kk += 8) {
            uint32_t a[2][4], b[8][2];
            #pragma unroll
            for (int i = 0; i < 2; i++) {
                int mb = warp_m + (i << 4);
                a[i][0] = __float_as_uint(As[kk + r][mb + g]);
                a[i][1] = __float_as_uint(As[kk + r][mb + g + 8]);
                a[i][2] = __float_as_uint(As[kk + r + 4][mb + g]);
                a[i][3] = __float_as_uint(As[kk + r + 4][mb + g + 8]);
            }
            #pragma unroll
            for (int j = 0; j < 8; j++) {
                int nb = warp_n + (j << 3);
                b[j][0] = __float_as_uint(Bs[kk + r][nb + g]);
                b[j][1] = __float_as_uint(Bs[kk + r + 4][nb + g]);
            }
            #pragma unroll
            for (int i = 0; i < 2; i++)
                #pragma unroll
                for (int j = 0; j < 8; j++)
                    asm volatile(
                        "mma.sync.aligned.m16n8k8.row.col.f32.tf32.tf32.f32 "
                        "{%0,%1,%2,%3}, {%4,%5,%6,%7}, {%8,%9}, {%0,%1,%2,%3};"
                        : "+f"(c[i][j][0]), "+f"(c[i][j][1]), "+f"(c[i][j][2]), "+f"(c[i][j][3])
                        : "r"(a[i][0]), "r"(a[i][1]), "r"(a[i][2]), "r"(a[i][3]),
                          "r"(b[j][0]), "r"(b[j][1]));
        }
        __syncthreads();
    }

    #pragma unroll
    for (int i = 0; i < 2; i++) {
        #pragma unroll
        for (int j = 0; j < 8; j++) {
            int col = n0 + warp_n + (j << 3) + (r << 1);
            int row0 = m0 + warp_m + (i << 4) + g;
            if (row0 < M) {
                C[(long)row0 * N + col]     = c[i][j][0];
                C[(long)row0 * N + col + 1] = c[i][j][1];
            }
            int row1 = row0 + 8;
            if (row1 < M) {
                C[(long)row1 * N + col]     = c[i][j][2];
                C[(long)row1 * N + col + 1] = c[i][j][3];
            }
        }
    }
}

// GEMV: out[m] = dot(A[m,:K], w[:K]), K multiple of 128, float4.
__global__ void gemv_kernel(const float* __restrict__ A, const float* __restrict__ w,
                            float* __restrict__ out, int M, int K) {
    int gt = blockIdx.x * blockDim.x + threadIdx.x;
    int row = gt >> 5, lane = gt & 31;
    if (row >= M) return;
    const float4* a4 = (const float4*)(A + (long)row * K);
    const float4* w4 = (const float4*)w;
    int K4 = K >> 2;
    float s = 0.f;
    for (int k = lane; k < K4; k += 32) {
        float4 a = a4[k], b = w4[k];
        s = fmaf(a.x, b.x, s); s = fmaf(a.y, b.y, s);
        s = fmaf(a.z, b.z, s); s = fmaf(a.w, b.w, s);
    }
    #pragma unroll
    for (int o = 16; o; o >>= 1) s += __shfl_xor_sync(0xffffffffu, s, o);
    if (lane == 0) out[row] = s;
}

// ---------------- FUSED logits + online-softmax + mean aggregate ----------------
// Warp per node. C=128. Lane owns one float4 per head. Single pass over edges.

__device__ __forceinline__ float leaky02(float v) { return v > 0.f ? v : 0.2f * v; }

// H = 2 (layer 1)
__global__ __launch_bounds__(256) void fused_agg_h2(
    const float* __restrict__ xl, const float* __restrict__ xr,
    const float* __restrict__ att,
    const int* __restrict__ rowptr, const int* __restrict__ csrsrc,
    const float* __restrict__ bias, float* __restrict__ out, int N) {
    int node = blockIdx.x * 8 + (threadIdx.x >> 5);
    if (node >= N) return;
    int lane = threadIdx.x & 31;
    const int HC4 = 64;

    const float4* xl4 = (const float4*)xl;
    const float4* xr4 = (const float4*)xr;
    const float4* at4 = (const float4*)att;
    const float4* b4  = (const float4*)bias;
    float4* out4 = (float4*)out;

    long base = (long)node * HC4 + lane;

    float4 xrv0 = xr4[base],      xrv1 = xr4[base + 32];
    float4 atv0 = at4[lane],      atv1 = at4[32 + lane];
    float4 bb0  = b4[lane],       bb1  = b4[32 + lane];

    int beg = rowptr[node], end = rowptr[node + 1];
    if (beg == end) {
        out4[base] = bb0;
        out4[base + 32] = bb1;
        return;
    }

    float m0 = -1e30f, s0 = 0.f, m1 = -1e30f, s1 = 0.f;
    float4 acc0 = make_float4(0.f, 0.f, 0.f, 0.f);
    float4 acc1 = make_float4(0.f, 0.f, 0.f, 0.f);

    for (int e = beg; e < end; e++) {
        int srcn = __ldg(&csrsrc[e]);
        long sb = (long)srcn * HC4 + lane;
        float4 v0 = xl4[sb], v1 = xl4[sb + 32];
        float t0, t1;
        t0  = leaky02(v0.x + xrv0.x) * atv0.x;
        t0 += leaky02(v0.y + xrv0.y) * atv0.y;
        t0 += leaky02(v0.z + xrv0.z) * atv0.z;
        t0 += leaky02(v0.w + xrv0.w) * atv0.w;
        t1  = leaky02(v1.x + xrv1.x) * atv1.x;
        t1 += leaky02(v1.y + xrv1.y) * atv1.y;
        t1 += leaky02(v1.z + xrv1.z) * atv1.z;
        t1 += leaky02(v1.w + xrv1.w) * atv1.w;
        #pragma unroll
        for (int o = 16; o; o >>= 1) {
            t0 += __shfl_xor_sync(0xffffffffu, t0, o);
            t1 += __shfl_xor_sync(0xffffffffu, t1, o);
        }
        {
            float nm = fmaxf(m0, t0);
            float sc = __expf(m0 - nm);
            float w  = __expf(t0 - nm);
            s0 = s0 * sc + w;
            acc0.x = acc0.x * sc + w * v0.x;
            acc0.y = acc0.y * sc + w * v0.y;
            acc0.z = acc0.z * sc + w * v0.z;
            acc0.w = acc0.w * sc + w * v0.w;
            m0 = nm;
        }
        {
            float nm = fmaxf(m1, t1);
            float sc = __expf(m1 - nm);
            float w  = __expf(t1 - nm);
            s1 = s1 * sc + w;
            acc1.x = acc1.x * sc + w * v1.x;
            acc1.y = acc1.y * sc + w * v1.y;
            acc1.z = acc1.z * sc + w * v1.z;
            acc1.w = acc1.w * sc + w * v1.w;
            m1 = nm;
        }
    }

    float degf = (float)(end - beg);
    {
        float inv = 1.f / (s0 * degf);
        float4 o;
        o.x = acc0.x * inv + bb0.x;
        o.y = acc0.y * inv + bb0.y;
        o.z = acc0.z * inv + bb0.z;
        o.w = acc0.w * inv + bb0.w;
        out4[base] = o;
    }
    {
        float inv = 1.f / (s1 * degf);
        float4 o;
        o.x = acc1.x * inv + bb1.x;
        o.y = acc1.y * inv + bb1.y;
        o.z = acc1.z * inv + bb1.z;
        o.w = acc1.w * inv + bb1.w;
        out4[base + 32] = o;
    }
}

// H = 1 (layer 2)
__global__ __launch_bounds__(256) void fused_agg_h1(
    const float* __restrict__ xl, const float* __restrict__ xr,
    const float* __restrict__ att,
    const int* __restrict__ rowptr, const int* __restrict__ csrsrc,
    const float* __restrict__ bias, float* __restrict__ out, int N) {
    int node = blockIdx.x * 8 + (threadIdx.x >> 5);
    if (node >= N) return;
    int lane = threadIdx.x & 31;
    const int HC4 = 32;

    const float4* xl4 = (const float4*)xl;
    const float4* xr4 = (const float4*)xr;
    const float4* at4 = (const float4*)att;
    const float4* b4  = (const float4*)bias;
    float4* out4 = (float4*)out;

    long base = (long)node * HC4 + lane;

    float4 xrv = xr4[base];
    float4 atv = at4[lane];
    float4 bb  = b4[lane];

    int beg = rowptr[node], end = rowptr[node + 1];
    if (beg == end) { out4[base] = bb; return; }

    float m = -1e30f, s = 0.f;
    float4 acc = make_float4(0.f, 0.f, 0.f, 0.f);

    for (int e = beg; e < end; e++) {
        int srcn = __ldg(&csrsrc[e]);
        float4 v = xl4[(long)srcn * HC4 + lane];
        float t;
        t  = leaky02(v.x + xrv.x) * atv.x;
        t += leaky02(v.y + xrv.y) * atv.y;
        t += leaky02(v.z + xrv.z) * atv.z;
        t += leaky02(v.w + xrv.w) * atv.w;
        #pragma unroll
        for (int o = 16; o; o >>= 1) t += __shfl_xor_sync(0xffffffffu, t, o);
        float nm = fmaxf(m, t);
        float sc = __expf(m - nm);
        float w  = __expf(t - nm);
        s = s * sc + w;
        acc.x = acc.x * sc + w * v.x;
        acc.y = acc.y * sc + w * v.y;
        acc.z = acc.z * sc + w * v.z;
        acc.w = acc.w * sc + w * v.w;
        m = nm;
    }

    float inv = 1.f / (s * (float)(end - beg));
    float4 o;
    o.x = acc.x * inv + bb.x;
    o.y = acc.y * inv + bb.y;
    o.z = acc.z * inv + bb.z;
    o.w = acc.w * inv + bb.w;
    out4[base] = o;
}

// Layer 3 fused (C=1): thread per node, scalar online softmax.
__global__ void fused_agg3_kernel(const float* __restrict__ xl, const float* __restrict__ xr,
                                  const float* __restrict__ att,
                                  const int* __restrict__ rowptr, const int* __restrict__ csrsrc,
                                  const float* __restrict__ bias, float* __restrict__ out, int N) {
    int node = blockIdx.x * blockDim.x + threadIdx.x;
    if (node >= N) return;
    int beg = rowptr[node], end = rowptr[node + 1];
    float b0 = bias[0];
    if (beg == end) { out[node] = b0; return; }
    float a0 = att[0];
    float xrn = xr[node];
    float m = -1e30f, s = 0.f, acc = 0.f;
    for (int e = beg; e < end; e++) {
        float v = xl[csrsrc[e]];
        float t = leaky02(v + xrn) * a0;
        float nm = fmaxf(m, t);
        float sc = __expf(m - nm);
        float w  = __expf(t - nm);
        s = s * sc + w;
        acc = acc * sc + w * v;
        m = nm;
    }
    out[node] = acc / (s * (float)(end - beg)) + b0;
}

// ---------------- Output gather ----------------

__global__ void gather_kernel(const float* __restrict__ h3, const float* __restrict__ y,
                              const int* __restrict__ tidx, int nt, int N,
                              float* __restrict__ out, int both) {
    int i = blockIdx.x * blockDim.x + threadIdx.x;
    if (i >= nt) return;
    int t = tidx[i];
    if (t < 0) t = 0;
    if (t >= N) t = N - 1;
    out[i] = 1.f / (1.f + __expf(-h3[t]));
    if (both) out[nt + i] = y[t];
}

// ---------------- Launch ----------------

extern "C" void kernel_launch(void* const* d_in, const int* in_sizes, int n_in,
                              void* d_out, int out_size) {
    const float* x    = (const float*)d_in[0];
    const int*   ei   = (const int*)d_in[1];
    const float* y    = (const float*)d_in[2];
    const int*   tidx = (const int*)d_in[3];
    const float* W1l = (const float*)d_in[4];
    const float* W1r = (const float*)d_in[5];
    const float* a1  = (const float*)d_in[6];
    const float* b1  = (const float*)d_in[7];
    const float* W2l = (const float*)d_in[8];
    const float* W2r = (const float*)d_in[9];
    const float* a2  = (const float*)d_in[10];
    const float* b2  = (const float*)d_in[11];
    const float* W3l = (const float*)d_in[12];
    const float* W3r = (const float*)d_in[13];
    const float* a3  = (const float*)d_in[14];
    const float* b3  = (const float*)d_in[15];

    int N  = in_sizes[2];
    int E  = in_sizes[1] / 2;
    int NT = in_sizes[3];
    int IN = in_sizes[0] / N;

    const int* src = ei;
    const int* dst = ei + E;

    float *p_xl, *p_xr, *p_h;
    int *p_rowptr, *p_cursor, *p_deg, *p_csrsrc;
    cudaGetSymbolAddress((void**)&p_xl, g_xl);
    cudaGetSymbolAddress((void**)&p_xr, g_xr);
    cudaGetSymbolAddress((void**)&p_h,  g_h);
    cudaGetSymbolAddress((void**)&p_rowptr, g_rowptr);
    cudaGetSymbolAddress((void**)&p_cursor, g_cursor);
    cudaGetSymbolAddress((void**)&p_deg,    g_deg);
    cudaGetSymbolAddress((void**)&p_csrsrc, g_csrsrc);

    // ---- CSR build (kernel-only) ----
    zero_kernel<<<(N + 255) / 256, 256>>>(p_deg, N);
    hist_kernel<<<(E + 255) / 256, 256>>>(dst, E, N, p_deg);
    scan_kernel<<<1, 1024>>>(p_deg, p_rowptr, p_cursor, N);
    scatter_kernel<<<(E + 255) / 256, 256>>>(src, dst, E, N, p_cursor, p_csrsrc);

    int gm = (N + TBM - 1) / TBM;
    int gn = (N + 7) / 8;

    // ---- Layer 1: 129 -> 256 (H=2, C=128) ----
    {
        dim3 g(256 / TBN, gm, 2);
        gemm_tf32_kernel<<<g, 256>>>(x, W1l, W1r, p_xl, p_xr, N, IN, 256);
        fused_agg_h2<<<gn, 256>>>(p_xl, p_xr, a1, p_rowptr, p_csrsrc, b1, p_h, N);
    }

    // ---- Layer 2: 256 -> 128 (H=1, C=128) ----
    {
        dim3 g(128 / TBN, gm, 2);
        gemm_tf32_kernel<<<g, 256>>>(p_h, W2l, W2r, p_xl, p_xr, N, 256, 128);
        fused_agg_h1<<<gn, 256>>>(p_xl, p_xr, a2, p_rowptr, p_csrsrc, b2, p_h, N);
    }

    // ---- Layer 3: 128 -> 1 (H=1, C=1) ----
    {
        gemv_kernel<<<(N * 32 + 255) / 256, 256>>>(p_h, W3l, p_xl, N, 128);
        gemv_kernel<<<(N * 32 + 255) / 256, 256>>>(p_h, W3r, p_xr, N, 128);
        fused_agg3_kernel<<<(N + 255) / 256, 256>>>(p_xl, p_xr, a3, p_rowptr, p_csrsrc, b3, p_h, N);
    }

    // ---- Output: pred[train_idx], y[train_idx] ----
    int both = (out_size >= 2 * NT) ? 1 : 0;
    gather_kernel<<<(NT + 255) / 256, 256>>>(p_h, y, tidx, NT, N, (float*)d_out, both);
}